// round 1
// baseline (speedup 1.0000x reference)
#include <cuda_runtime.h>
#include <math.h>

// Problem constants
#define BB 8
#define LL 2048
#define DD 1024
#define FF 4096
#define MM (BB*LL)        // 16384 rows
#define TOPK 7
#define LMASK (LL-1)

// ---------------- scratch (device globals; no allocation) ----------------
__device__ float g_q[(size_t)MM*DD];            // q  -> later attn out
__device__ float g_k[(size_t)MM*DD];            // k  -> later x1
__device__ float g_v[(size_t)MM*DD];            // v  -> later y (c2 out)
__device__ float g_G[(size_t)BB*LL*LL];         // Gram -> later roll output (first 64MB)
__device__ float g_h[(size_t)MM*FF];            // FFN hidden
__device__ float g_part[BB*8*LL];               // lag partial sums
__device__ float g_mv[BB*LL];                   // mean_value
__device__ float g_w[BB*8];                     // softmax weights
__device__ int   g_delay[8];                    // delays (from batch 0)

// ---------------- generic fp32 SGEMM: C = A(MxK) * B + bias (+relu) ------
// TRANSB=false: B is K x N row-major.  TRANSB=true: B is N x K row-major.
template<bool TRANSB, bool RELU>
__global__ __launch_bounds__(256)
void sgemm(const float* __restrict__ A, const float* __restrict__ B,
           float* __restrict__ C, const float* __restrict__ bias,
           int M, int N, int K, size_t sA, size_t sB, size_t sC)
{
    A += (size_t)blockIdx.z * sA;
    B += (size_t)blockIdx.z * sB;
    C += (size_t)blockIdx.z * sC;

    __shared__ float As[8][128];
    __shared__ float Bs[8][128];

    const int tid = threadIdx.x;
    const int bm  = blockIdx.y * 128;
    const int bn  = blockIdx.x * 128;
    const int tx  = (tid & 15) * 8;     // 0..120
    const int ty  = (tid >> 4) * 8;     // 0..120
    const int lr  = tid >> 1;           // 0..127 (A / transB load row)
    const int lc  = (tid & 1) * 4;      // 0 or 4
    const int br  = tid >> 5;           // 0..7  (B load row, non-trans)
    const int bc  = (tid & 31) * 4;     // 0..124

    float acc[8][8];
    #pragma unroll
    for (int i = 0; i < 8; i++)
        #pragma unroll
        for (int j = 0; j < 8; j++) acc[i][j] = 0.f;

    for (int k0 = 0; k0 < K; k0 += 8) {
        float4 a4 = *(const float4*)(A + (size_t)(bm + lr) * K + k0 + lc);
        As[lc+0][lr] = a4.x; As[lc+1][lr] = a4.y;
        As[lc+2][lr] = a4.z; As[lc+3][lr] = a4.w;
        if (TRANSB) {
            float4 b4 = *(const float4*)(B + (size_t)(bn + lr) * K + k0 + lc);
            Bs[lc+0][lr] = b4.x; Bs[lc+1][lr] = b4.y;
            Bs[lc+2][lr] = b4.z; Bs[lc+3][lr] = b4.w;
        } else {
            float4 b4 = *(const float4*)(B + (size_t)(k0 + br) * N + bn + bc);
            *(float4*)&Bs[br][bc] = b4;
        }
        __syncthreads();
        #pragma unroll
        for (int kk = 0; kk < 8; kk++) {
            float4 a0 = *(const float4*)&As[kk][ty];
            float4 a1 = *(const float4*)&As[kk][ty+4];
            float4 b0 = *(const float4*)&Bs[kk][tx];
            float4 b1 = *(const float4*)&Bs[kk][tx+4];
            float af[8] = {a0.x,a0.y,a0.z,a0.w,a1.x,a1.y,a1.z,a1.w};
            float bf[8] = {b0.x,b0.y,b0.z,b0.w,b1.x,b1.y,b1.z,b1.w};
            #pragma unroll
            for (int i = 0; i < 8; i++)
                #pragma unroll
                for (int j = 0; j < 8; j++)
                    acc[i][j] = fmaf(af[i], bf[j], acc[i][j]);
        }
        __syncthreads();
    }

    #pragma unroll
    for (int i = 0; i < 8; i++) {
        size_t row = (size_t)(bm + ty + i);
        #pragma unroll
        for (int j = 0; j < 8; j += 4) {
            float4 o;
            o.x = acc[i][j+0]; o.y = acc[i][j+1];
            o.z = acc[i][j+2]; o.w = acc[i][j+3];
            if (bias) {
                o.x += bias[bn+tx+j+0]; o.y += bias[bn+tx+j+1];
                o.z += bias[bn+tx+j+2]; o.w += bias[bn+tx+j+3];
            }
            if (RELU) {
                o.x = fmaxf(o.x, 0.f); o.y = fmaxf(o.y, 0.f);
                o.z = fmaxf(o.z, 0.f); o.w = fmaxf(o.w, 0.f);
            }
            *(float4*)(C + row * N + bn + tx + j) = o;
        }
    }
}

// ---- mean_value: wrapped-diagonal reduction of the Gram matrix ----------
// g_part[b][tc][l] = sum_{t in chunk tc} G[b][t][(t-l) & LMASK]
__global__ void lag_partial()
{
    int b  = blockIdx.z;
    int tc = blockIdx.y;
    int l  = blockIdx.x * 256 + threadIdx.x;
    const float* Gb = g_G + (size_t)b * LL * LL;
    int t0 = tc * 256;
    float s = 0.f;
    #pragma unroll 4
    for (int t = t0; t < t0 + 256; ++t)
        s += Gb[(size_t)t * LL + ((t - l) & LMASK)];
    g_part[(b * 8 + tc) * LL + l] = s;
}

__global__ void lag_reduce()
{
    int idx = blockIdx.x * 256 + threadIdx.x;   // b*LL + l
    int b = idx >> 11;
    int l = idx & LMASK;
    float s = 0.f;
    #pragma unroll
    for (int tc = 0; tc < 8; tc++) s += g_part[(b * 8 + tc) * LL + l];
    g_mv[idx] = s * (1.f / (float)DD);
}

// ---- top-7 + softmax (per batch); batch 0 publishes delays --------------
__global__ void topk_softmax()
{
    int b = blockIdx.x;
    int tid = threadIdx.x;
    __shared__ float vals[LL];
    __shared__ float rv[256];
    __shared__ int   ri[256];
    __shared__ float topv[TOPK];
    __shared__ int   topi[TOPK];

    for (int i = tid; i < LL; i += 256) vals[i] = g_mv[b * LL + i];
    __syncthreads();

    for (int it = 0; it < TOPK; ++it) {
        float bv = -INFINITY; int bi = 0;
        for (int i = tid; i < LL; i += 256) {
            float v = vals[i];
            if (v > bv) { bv = v; bi = i; }
        }
        rv[tid] = bv; ri[tid] = bi;
        __syncthreads();
        for (int s = 128; s > 0; s >>= 1) {
            if (tid < s) {
                if (rv[tid+s] > rv[tid] ||
                    (rv[tid+s] == rv[tid] && ri[tid+s] < ri[tid])) {
                    rv[tid] = rv[tid+s]; ri[tid] = ri[tid+s];
                }
            }
            __syncthreads();
        }
        if (tid == 0) {
            topv[it] = rv[0]; topi[it] = ri[0];
            vals[ri[0]] = -INFINITY;
        }
        __syncthreads();
    }

    if (tid == 0) {
        float mx = topv[0];
        float e[TOPK], s = 0.f;
        #pragma unroll
        for (int i = 0; i < TOPK; i++) { e[i] = expf(topv[i] - mx); s += e[i]; }
        float inv = 1.f / s;
        #pragma unroll
        for (int i = 0; i < TOPK; i++) g_w[b * 8 + i] = e[i] * inv;
        if (b == 0)
            #pragma unroll
            for (int i = 0; i < TOPK; i++) g_delay[i] = topi[i];
    }
}

// ---- delay-aggregated value: out[b,l,:] = sum_i w[b,i]*v[b,(l+d_i)%L,:] --
// output written into g_G (Gram no longer needed)
__global__ void roll_combine()
{
    int l = blockIdx.x, b = blockIdx.y;
    int tid = threadIdx.x;
    float w[TOPK]; int rows[TOPK];
    #pragma unroll
    for (int i = 0; i < TOPK; i++) {
        w[i] = g_w[b * 8 + i];
        rows[i] = (l + g_delay[i]) & LMASK;
    }
    int d = tid * 4;
    float4 acc = make_float4(0.f, 0.f, 0.f, 0.f);
    #pragma unroll
    for (int i = 0; i < TOPK; i++) {
        float4 v4 = *(const float4*)(g_v + ((size_t)(b * LL + rows[i])) * DD + d);
        acc.x = fmaf(w[i], v4.x, acc.x);
        acc.y = fmaf(w[i], v4.y, acc.y);
        acc.z = fmaf(w[i], v4.z, acc.z);
        acc.w = fmaf(w[i], v4.w, acc.w);
    }
    *(float4*)(g_G + ((size_t)(b * LL + l)) * DD + d) = acc;
}

// ---- out = LayerNorm(A + B) * gamma + beta (row = 1024) ------------------
__global__ void add_ln(const float* __restrict__ A, const float* __restrict__ Bv,
                       const float* __restrict__ gamma, const float* __restrict__ beta,
                       float* __restrict__ out)
{
    int row = blockIdx.x;
    int tid = threadIdx.x;
    const float* pa = A  + (size_t)row * DD;
    const float* pb = Bv + (size_t)row * DD;
    __shared__ float red[256];

    float v[4];
    float s = 0.f;
    #pragma unroll
    for (int j = 0; j < 4; j++) {
        int c = tid + j * 256;
        v[j] = pa[c] + pb[c];
        s += v[j];
    }
    red[tid] = s; __syncthreads();
    for (int st = 128; st > 0; st >>= 1) {
        if (tid < st) red[tid] += red[tid + st];
        __syncthreads();
    }
    float mean = red[0] * (1.f / (float)DD);
    __syncthreads();

    float vs = 0.f;
    #pragma unroll
    for (int j = 0; j < 4; j++) { float d = v[j] - mean; vs += d * d; }
    red[tid] = vs; __syncthreads();
    for (int st = 128; st > 0; st >>= 1) {
        if (tid < st) red[tid] += red[tid + st];
        __syncthreads();
    }
    float rstd = rsqrtf(red[0] * (1.f / (float)DD) + 1e-6f);

    float* po = out + (size_t)row * DD;
    #pragma unroll
    for (int j = 0; j < 4; j++) {
        int c = tid + j * 256;
        po[c] = (v[j] - mean) * rstd * gamma[c] + beta[c];
    }
}

// -------------------------------------------------------------------------
extern "C" void kernel_launch(void* const* d_in, const int* in_sizes, int n_in,
                              void* d_out, int out_size)
{
    const float* x     = (const float*)d_in[0];
    const float* Wq    = (const float*)d_in[1];
    const float* bq    = (const float*)d_in[2];
    const float* Wk    = (const float*)d_in[3];
    const float* bk    = (const float*)d_in[4];
    const float* Wv    = (const float*)d_in[5];
    const float* bv    = (const float*)d_in[6];
    const float* Wo    = (const float*)d_in[7];
    const float* bo    = (const float*)d_in[8];
    const float* ln1g  = (const float*)d_in[9];
    const float* ln1b  = (const float*)d_in[10];
    const float* c1w   = (const float*)d_in[11];
    const float* c1b   = (const float*)d_in[12];
    const float* c2w   = (const float*)d_in[13];
    const float* c2b   = (const float*)d_in[14];
    const float* ln2g  = (const float*)d_in[15];
    const float* ln2b  = (const float*)d_in[16];
    float* out = (float*)d_out;

    float *q, *k, *v, *G, *h;
    cudaGetSymbolAddress((void**)&q, g_q);
    cudaGetSymbolAddress((void**)&k, g_k);
    cudaGetSymbolAddress((void**)&v, g_v);
    cudaGetSymbolAddress((void**)&G, g_G);
    cudaGetSymbolAddress((void**)&h, g_h);

    // 1) QKV projections (fp32 GEMMs)
    sgemm<false,false><<<dim3(DD/128, MM/128, 1), 256>>>(x, Wq, q, bq, MM, DD, DD, 0, 0, 0);
    sgemm<false,false><<<dim3(DD/128, MM/128, 1), 256>>>(x, Wk, k, bk, MM, DD, DD, 0, 0, 0);
    sgemm<false,false><<<dim3(DD/128, MM/128, 1), 256>>>(x, Wv, v, bv, MM, DD, DD, 0, 0, 0);

    // 2) Per-batch Gram matrix G[b] = q[b] * k[b]^T   (replaces the FFT)
    sgemm<true,false><<<dim3(LL/128, LL/128, BB), 256>>>(
        q, k, G, nullptr, LL, LL, DD,
        (size_t)LL*DD, (size_t)LL*DD, (size_t)LL*LL);

    // 3) mean_value[b,l] = (1/D) * sum_t G[b,t,(t-l) mod L]
    lag_partial<<<dim3(LL/256, 8, BB), 256>>>();
    lag_reduce<<<(BB*LL)/256, 256>>>();

    // 4) top-7 + softmax weights; batch-0 delays
    topk_softmax<<<BB, 256>>>();

    // 5) delay aggregation of v  (result reuses g_G)
    roll_combine<<<dim3(LL, BB), 256>>>();

    // 6) attn = roll_out @ Wo + bo  (into g_q)
    sgemm<false,false><<<dim3(DD/128, MM/128, 1), 256>>>(G, Wo, q, bo, MM, DD, DD, 0, 0, 0);

    // 7) x1 = LN(x + attn)  (into g_k)
    add_ln<<<MM, 256>>>(x, q, ln1g, ln1b, k);

    // 8) FFN: h = relu(x1 @ c1_w + c1_b)
    sgemm<false,true><<<dim3(FF/128, MM/128, 1), 256>>>(k, c1w, h, c1b, MM, FF, DD, 0, 0, 0);

    // 9) y = h @ c2_w + c2_b  (into g_v)
    sgemm<false,false><<<dim3(DD/128, MM/128, 1), 256>>>(h, c2w, v, c2b, MM, DD, FF, 0, 0, 0);

    // 10) out = LN(x1 + y)
    add_ln<<<MM, 256>>>(k, v, ln2g, ln2b, out);
}